// round 16
// baseline (speedup 1.0000x reference)
#include <cuda_runtime.h>
#include <math.h>

#define Bq 8
#define Cc 64
#define Ll 784
#define HIDd 128
#define Sdim 64
#define NHh 16
#define DIMc 256
#define PT 49
#define NTt 16
#define NBLK 148
#define THR 512
#define NE (Bq*Cc*Ll)

// ---------------- scratch ----------------
__device__ float g_x1o [Bq*Cc*Ll];
__device__ float g_x1g [Bq*Cc*Ll];
__device__ float g_b1  [Bq*Cc*Ll];
__device__ float g_b2  [Bq*Cc*Ll];
__device__ float g_bcdt1[Bq*192*Ll];
__device__ float g_wsl [Bq*Sdim*Ll];
__device__ float g_h2  [Bq*Cc*Sdim];
__device__ float g_b3  [Bq*Cc*Ll];
__device__ float g_qb  [Bq*NHh*Ll*4];
__device__ float g_kb  [Bq*NHh*Ll*4];
__device__ float g_vb  [Bq*NHh*Ll*4];
__device__ float g_ob  [Bq*Ll*Cc];
__device__ float g_b4  [Bq*Cc*Ll];
__device__ float g_m1  [Bq*HIDd*Ll];

// ---------------- grid barrier ----------------
__device__ unsigned int g_barcnt = 0;
__device__ volatile unsigned int g_bargen = 0;

__device__ __forceinline__ void gridsync(){
    __syncthreads();
    if (threadIdx.x == 0){
        __threadfence();
        unsigned int gen = g_bargen;
        unsigned int t = atomicInc(&g_barcnt, NBLK - 1u);
        if (t == NBLK - 1u){
            __threadfence();
            g_bargen = gen + 1u;
        } else {
            while (g_bargen == gen){}
        }
        __threadfence();
    }
    __syncthreads();
}

__device__ __forceinline__ float bnf(float x, const float* __restrict__ p, int c, int C){
    return (x - p[2*C+c]) * p[c] * rsqrtf(p[3*C+c] + 1e-5f) + p[C+c];
}

__device__ __forceinline__ unsigned long long pk2(float a, float b){
    unsigned long long r; asm("mov.b64 %0, {%1,%2};" : "=l"(r) : "f"(a), "f"(b)); return r;
}
__device__ __forceinline__ void upk2(unsigned long long v, float& a, float& b){
    asm("mov.b64 {%0,%1}, %2;" : "=f"(a), "=f"(b) : "l"(v));
}
__device__ __forceinline__ unsigned long long fma2(unsigned long long a, unsigned long long b, unsigned long long c){
    unsigned long long r; asm("fma.rn.f32x2 %0, %1, %2, %3;" : "=l"(r) : "l"(a), "l"(b), "l"(c)); return r;
}
__device__ __forceinline__ unsigned long long mul2(unsigned long long a, unsigned long long b){
    unsigned long long r; asm("mul.rn.f32x2 %0, %1, %2;" : "=l"(r) : "l"(a), "l"(b)); return r;
}

// =======================================================================
// persistent mega-kernel
// =======================================================================
__global__ void __launch_bounds__(THR,1)
k_all(const float* __restrict__ x,
      const float* __restrict__ dw1_w, const float* __restrict__ dw1_b,
      const float* __restrict__ bn_dw1,
      const float* __restrict__ f1w, const float* __restrict__ f1b,
      const float* __restrict__ f2w, const float* __restrict__ f2b,
      const float* __restrict__ gw,  const float* __restrict__ gb,
      const float* __restrict__ bng,
      const float* __restrict__ dw2_w, const float* __restrict__ dw2_b,
      const float* __restrict__ wh1, const float* __restrict__ wv1,
      const float* __restrict__ wh2, const float* __restrict__ wv2,
      const float* __restrict__ bnm,
      const float* __restrict__ bcdt_w, const float* __restrict__ ssd_dw,
      const float* __restrict__ hzw, const float* __restrict__ outw,
      const float* __restrict__ Ap, const float* __restrict__ Dp,
      const float* __restrict__ qkv_w, const float* __restrict__ proj_w,
      const float* __restrict__ bn4,
      const float* __restrict__ mlp1_w, const float* __restrict__ bn_m,
      const float* __restrict__ mlp2_w, const float* __restrict__ bn1,
      float* __restrict__ out){
    extern __shared__ float pool[];
    int bid = blockIdx.x;
    int tid = threadIdx.x;

    // ============ PHASE 0: dw7a | att2 | bcdt | qkv ============
    // dw7a (elementwise, no smem)
    for (int idx = bid*THR + tid; idx < NE; idx += NBLK*THR){
        int p = idx % Ll; int c = (idx/Ll) % Cc; int b = idx/(Ll*Cc);
        int y = p/28, xx = p%28;
        const float* ip = x + ((size_t)(b*DIMc + c))*Ll;
        const float* wc = dw1_w + c*49;
        float acc = dw1_b[c];
        #pragma unroll
        for (int ky=0; ky<7; ky++){
            int yy = y+ky-3; if ((unsigned)yy >= 28u) continue;
            #pragma unroll
            for (int kx=0; kx<7; kx++){
                int xw = xx+kx-3; if ((unsigned)xw >= 28u) continue;
                acc += wc[ky*7+kx] * ip[yy*28+xw];
            }
        }
        g_x1o[idx] = bnf(acc, bn_dw1, c, Cc);
    }
    // att2 tasks (512)
    for (int t = bid; t < 512; t += NBLK){
        float* mp   = pool;          // 784
        float* xt   = pool + 784;
        float* sacc = pool + 884;
        float* sh   = pool + 984;
        float* cbuf = pool + 1174;
        float* sw1  = pool + 1364;
        float* sw2  = pool + 1397;
        float* sw3  = pool + 1430;
        float* sw4  = pool + 1463;
        int b = t/64, c = t%64;
        __syncthreads();
        if (tid < 33){ sw1[tid]=wh1[c*33+tid]; sw2[tid]=wv1[c*33+tid];
                       sw3[tid]=wh2[c*33+tid]; sw4[tid]=wv2[c*33+tid]; }
        const float* x2 = x + ((size_t)(b*DIMc + 64 + c))*Ll;
        for (int p=tid; p<784; p+=THR){
            int y=p/28, xx=p%28;
            float m = -1e30f;
            #pragma unroll
            for (int dy=-1; dy<=1; dy++){ int yy=y+dy; if ((unsigned)yy>=28u) continue;
                #pragma unroll
                for (int dx=-1; dx<=1; dx++){ int xw=xx+dx; if ((unsigned)xw>=28u) continue;
                    m = fmaxf(m, x2[yy*28+xw]); } }
            mp[p] = m;
        }
        __syncthreads();
        if (tid < 100){
            int oy = tid/10, ox = tid%10;
            const float fa[4] = {1.f,3.f,3.f,1.f};
            float acc = 0.f;
            #pragma unroll
            for (int ty=0; ty<4; ty++){
                int q = 3*oy + ty - 1; if (q < 0) q = -q; if (q >= 28) q = 54 - q;
                #pragma unroll
                for (int tx=0; tx<4; tx++){
                    int r = 3*ox + tx - 1; if (r < 0) r = -r; if (r >= 28) r = 54 - r;
                    acc += fa[ty]*fa[tx]*mp[q*28+r];
                }
            }
            xt[tid] = acc * (1.0f/64.0f);
        }
        __syncthreads();
        if (tid < 100){
            int y = tid/10, xo = tid%10;
            float s = 0.f;
            #pragma unroll
            for (int ky=0; ky<11; ky++){ int yy=y+ky-5; if ((unsigned)yy>=10u) continue;
                #pragma unroll
                for (int kx=0; kx<3; kx++){ int xx=xo+kx-1; if ((unsigned)xx>=10u) continue;
                    s += sw1[ky*3+kx]*xt[yy*10+xx]; } }
            #pragma unroll
            for (int ky=0; ky<3; ky++){ int yy=y+ky-1; if ((unsigned)yy>=10u) continue;
                #pragma unroll
                for (int kx=0; kx<11; kx++){ int xx=xo+kx-5; if ((unsigned)xx>=10u) continue;
                    s += sw2[ky*11+kx]*xt[yy*10+xx]; } }
            sacc[tid] = s;
        }
        if (tid < 190){
            int r = tid/19, j = tid%19, d = j - r;
            sh[tid] = (d >= 0 && d < 10) ? xt[r*10 + d] : 0.f;
        }
        __syncthreads();
        if (tid < 190){
            int u = tid/19, v = tid%19;
            float s = 0.f;
            #pragma unroll
            for (int ky=0; ky<11; ky++){ int uu=u+ky-5; if ((unsigned)uu>=10u) continue;
                #pragma unroll
                for (int kx=0; kx<3; kx++){ int vv=v+kx-1; if ((unsigned)vv>=19u) continue;
                    s += sw3[ky*3+kx]*sh[uu*19+vv]; } }
            cbuf[tid] = s;
        }
        __syncthreads();
        if (tid < 100){
            int y = tid/10, xo = tid%10;
            sacc[tid] += cbuf[20*y + xo];
        }
        __syncthreads();
        if (tid < 190){
            int a = tid/10, b2 = tid%10, d = a - b2;
            sh[tid] = (d >= 0 && d < 10) ? xt[d*10 + b2] : 0.f;
        }
        __syncthreads();
        if (tid < 190){
            int a = tid/10, b2 = tid%10;
            float s = 0.f;
            #pragma unroll
            for (int ky=0; ky<3; ky++){ int av=a+ky-1; if ((unsigned)av>=19u) continue;
                #pragma unroll
                for (int kx=0; kx<11; kx++){ int bv=b2+kx-5; if ((unsigned)bv>=10u) continue;
                    s += sw4[ky*11+kx]*sh[av*10+bv]; } }
            cbuf[tid] = s;
        }
        __syncthreads();
        if (tid < 100){
            int y = tid/10, xo = tid%10;
            int g = 20*xo + y;
            float s = sacc[tid] + cbuf[(g%19)*10 + (g/19)];
            s = bnf(s, bnm, c, 64);
            sacc[tid] = 1.f/(1.f + __expf(-s));
        }
        __syncthreads();
        float* op = g_b2 + (size_t)t*Ll;
        for (int p=tid; p<Ll; p+=THR){
            int y = p/28, xx = p%28;
            op[p] = x2[p] * sacc[(y*10/28)*10 + (xx*10/28)];
        }
    }
    // bcdt + qkv tasks (2 x 128), pw 192x64 weight-stationary
    for (int tt = bid; tt < 256; tt += NBLK){
        int isQ = tt >= 128;
        int t = isQ ? tt-128 : tt;
        const float* w = isQ ? qkv_w : bcdt_w;
        int chOff = isQ ? 192 : 128;
        float* sw = pool;            // 192*65
        float* sx = pool + 192*65;   // 64*49
        int b = t / NTt, p0 = (t % NTt) * PT;
        __syncthreads();
        for (int i=tid; i<192*64; i+=THR){ sw[(i/64)*65 + (i%64)] = w[i]; }
        for (int i=tid; i<64*PT; i+=THR){
            int c=i/PT, px=i%PT;
            sx[i] = x[((size_t)(b*DIMc + chOff + c))*Ll + p0+px];
        }
        __syncthreads();
        int og = tid % 48, pg = tid / 48;   // 48 x up-to-10 (use 10 px-groups of 5)
        int o0 = og*4, px0 = pg*5;
        int cnt = PT - px0; if (cnt > 5) cnt = 5; if (cnt < 0) cnt = 0;
        float acc[4][5];
        #pragma unroll
        for (int k=0;k<4;k++)
            #pragma unroll
            for (int j=0;j<5;j++) acc[k][j]=0.f;
        if (cnt > 0){
            for (int c=0;c<64;c++){
                float w0=sw[(o0+0)*65+c], w1=sw[(o0+1)*65+c], w2=sw[(o0+2)*65+c], w3=sw[(o0+3)*65+c];
                #pragma unroll 5
                for (int j=0;j<5;j++){
                    if (j<cnt){
                        float xx = sx[c*PT + px0 + j];
                        acc[0][j]+=w0*xx; acc[1][j]+=w1*xx; acc[2][j]+=w2*xx; acc[3][j]+=w3*xx;
                    }
                }
            }
            if (!isQ){
                #pragma unroll
                for (int k=0;k<4;k++)
                    for (int j=0;j<cnt;j++)
                        g_bcdt1[((size_t)(b*192 + o0+k))*Ll + p0+px0+j] = acc[k][j];
            } else {
                #pragma unroll
                for (int k=0;k<4;k++){
                    int o = o0+k;
                    int part = o/64, rem = o%64, hh = rem/4, dd = rem%4;
                    float* dst = (part==0) ? g_qb : (part==1) ? g_kb : g_vb;
                    for (int j=0;j<cnt;j++)
                        dst[(((size_t)b*16 + hh)*Ll + p0+px0+j)*4 + dd] = acc[k][j];
                }
            }
        }
    }
    gridsync();

    // ============ PHASE 1: star | softAB | attn ============
    for (int t = bid; t < 128; t += NBLK){
        float* sxv = pool;            // 3136
        float* sa  = pool + 3136;     // 6272
        float* wb1 = pool + 9408;     // 8192
        float* wb2 = pool + 17600;    // 8192
        int b = t/16, p0 = (t%16)*PT;
        __syncthreads();
        for (int i=tid; i<64*PT; i+=THR){
            int c=i/PT, px=i%PT;
            sxv[i] = g_x1o[((size_t)(b*64+c))*Ll + p0+px];
        }
        for (int i=tid; i<8192; i+=THR){ wb1[i] = f1w[i]; wb2[i] = f2w[i]; }
        __syncthreads();
        for (int i=tid; i<128*PT; i+=THR){
            int h=i/PT, px=i%PT;
            float a = f1b[h], a2 = f2b[h];
            const float* w1 = wb1 + h*64;
            const float* w2 = wb2 + h*64;
            #pragma unroll 8
            for (int c=0;c<64;c++){ float xc = sxv[c*PT+px]; a += w1[c]*xc; a2 += w2[c]*xc; }
            a = fminf(fmaxf(a,0.f),6.f);
            sa[i] = a*a2;
        }
        __syncthreads();
        for (int i=tid; i<8192; i+=THR) wb1[i] = gw[i];
        __syncthreads();
        for (int i=tid; i<64*PT; i+=THR){
            int o=i/PT, px=i%PT;
            float acc = gb[o];
            const float* wr = wb1 + o*128;
            #pragma unroll 8
            for (int j=0;j<128;j++) acc += wr[j]*sa[j*PT+px];
            g_x1g[((size_t)(b*64+o))*Ll + p0+px] = bnf(acc, bng, o, 64);
        }
    }
    // softAB tasks (512): 2 px per thread
    for (int t = bid; t < 512; t += NBLK){
        float* rb  = pool;          // 784
        float* rd  = pool + 784;
        float* red = pool + 1568;   // 16
        int b = t/64, s = t%64;
        __syncthreads();
        for (int i=tid; i<784; i+=THR){
            rb[i] = g_bcdt1[((size_t)(b*192 + s))*Ll + i];
            rd[i] = g_bcdt1[((size_t)(b*192 + 128 + s))*Ll + i];
        }
        __syncthreads();
        const float* wB = ssd_dw + s*9;
        const float* wD = ssd_dw + (128+s)*9;
        float av = Ap[s];
        float dtv[2] = {-1e30f, -1e30f}, bmv[2] = {0.f, 0.f};
        #pragma unroll
        for (int k=0;k<2;k++){
            int p = tid + k*THR;
            if (p < 784){
                int y = p/28, xx = p%28;
                float ab = 0.f, ad = 0.f;
                #pragma unroll
                for (int ky=0; ky<3; ky++){
                    int yy=y+ky-1; if ((unsigned)yy>=28u) continue;
                    #pragma unroll
                    for (int kx=0; kx<3; kx++){
                        int xw=xx+kx-1; if ((unsigned)xw>=28u) continue;
                        ab += wB[ky*3+kx]*rb[yy*28+xw];
                        ad += wD[ky*3+kx]*rd[yy*28+xw];
                    }
                }
                bmv[k] = ab;
                dtv[k] = ad + av;
            }
        }
        float lm = fmaxf(dtv[0], dtv[1]);
        #pragma unroll
        for (int o=16;o;o>>=1) lm = fmaxf(lm, __shfl_xor_sync(0xFFFFFFFFu, lm, o));
        if ((tid&31)==0) red[tid>>5] = lm;
        __syncthreads();
        if (tid < 32){
            float v = (tid<16)? red[tid] : -1e30f;
            #pragma unroll
            for (int o=8;o;o>>=1) v = fmaxf(v, __shfl_xor_sync(0xFFFFFFFFu, v, o));
            if (tid==0) red[0]=v;
        }
        __syncthreads();
        float m = red[0];
        __syncthreads();
        float e0 = __expf(dtv[0]-m);
        float e1 = (tid+THR < 784) ? __expf(dtv[1]-m) : 0.f;
        float sum = e0 + e1;
        #pragma unroll
        for (int o=16;o;o>>=1) sum += __shfl_xor_sync(0xFFFFFFFFu, sum, o);
        if ((tid&31)==0) red[tid>>5] = sum;
        __syncthreads();
        if (tid < 32){
            float v = (tid<16)? red[tid] : 0.f;
            #pragma unroll
            for (int o=8;o;o>>=1) v += __shfl_xor_sync(0xFFFFFFFFu, v, o);
            if (tid==0) red[0]=v;
        }
        __syncthreads();
        float inv = 1.f/red[0];
        float* wo = g_wsl + ((size_t)(b*64 + s))*Ll;
        wo[tid] = e0 * inv * bmv[0];
        if (tid + THR < 784) wo[tid+THR] = e1 * inv * bmv[1];
    }
    // attn tasks (128)
    for (int t = bid; t < 128; t += NBLK){
        ulonglong2* KV = (ulonglong2*)pool;
        ulonglong2* VV = KV + Ll;
        size_t base4 = (size_t)t * Ll;
        __syncthreads();
        for (int i=tid; i<Ll; i+=THR){
            KV[i] = ((const ulonglong2*)g_kb)[base4 + i];
            VV[i] = ((const ulonglong2*)g_vb)[base4 + i];
        }
        __syncthreads();
        int b = t/16, hh = t%16;
        for (int q = tid; q < Ll; q += THR){
            float4 qv = ((const float4*)g_qb)[base4 + q];
            const float CS = 0.7213475204444817f;
            unsigned long long q01 = pk2(qv.x*CS, qv.y*CS);
            unsigned long long q23 = pk2(qv.z*CS, qv.w*CS);
            unsigned long long a01 = pk2(0.f,0.f), a23 = pk2(0.f,0.f);
            float den = 0.f;
            #pragma unroll 4
            for (int j=0; j<Ll; j++){
                ulonglong2 kk = KV[j];
                ulonglong2 vv = VV[j];
                unsigned long long pr = fma2(q23, kk.y, mul2(q01, kk.x));
                float lo, hi; upk2(pr, lo, hi);
                float s = lo + hi;
                float e; asm("ex2.approx.f32 %0, %1;" : "=f"(e) : "f"(s));
                unsigned long long ee = pk2(e, e);
                a01 = fma2(ee, vv.x, a01);
                a23 = fma2(ee, vv.y, a23);
                den += e;
            }
            float inv = __frcp_rn(den);
            float a0,a1,a2,a3;
            upk2(a01,a0,a1); upk2(a23,a2,a3);
            float4 r; r.x=a0*inv; r.y=a1*inv; r.z=a2*inv; r.w=a3*inv;
            ((float4*)g_ob)[(((size_t)b*Ll + q)*64 + hh*4)/4] = r;
        }
    }
    gridsync();

    // ============ PHASE 2: dw7b | ssdh | proj ============
    for (int idx = bid*THR + tid; idx < NE; idx += NBLK*THR){
        int p = idx % Ll; int c = (idx/Ll) % Cc; int b = idx/(Ll*Cc);
        int y = p/28, xx = p%28;
        const float* ip = g_x1g + ((size_t)(b*Cc + c))*Ll;
        const float* wc = dw2_w + c*49;
        float acc = dw2_b[c];
        #pragma unroll
        for (int ky=0; ky<7; ky++){
            int yy = y+ky-3; if ((unsigned)yy >= 28u) continue;
            #pragma unroll
            for (int kx=0; kx<7; kx++){
                int xw = xx+kx-3; if ((unsigned)xw >= 28u) continue;
                acc += wc[ky*7+kx] * ip[yy*28+xw];
            }
        }
        g_b1[idx] = acc;
    }
    // ssdh tasks (16)
    for (int t = bid; t < 16; t += NBLK){
        float* sxb = pool;                 // 6336
        float* swl = pool + 6336;          // 3168
        float* shh = pool + 9504;          // 2112
        float* wz  = pool + 11616;         // 8320
        float* zz  = pool + 19936;         // 4224
        int b = t >> 1, sh = t & 1;
        __syncthreads();
        int c0 = (tid & 15)*4, s0 = tid >> 4;    // s0 in 0..31
        float hacc[4] = {0.f,0.f,0.f,0.f};
        for (int ch=0; ch<8; ch++){
            int l0 = ch*98;
            for (int i=tid; i<64*98; i+=THR){
                int c=i/98, l=i%98;
                sxb[c*99+l] = x[((size_t)(b*DIMc + 128 + c))*Ll + l0 + l];
            }
            for (int i=tid; i<32*98; i+=THR){
                int sr=i/98, l=i%98;
                swl[sr*99+l] = g_wsl[((size_t)(b*64 + sh*32 + sr))*Ll + l0 + l];
            }
            __syncthreads();
            #pragma unroll 2
            for (int l=0; l<98; l++){
                float w0 = swl[s0*99+l];
                #pragma unroll
                for (int k=0;k<4;k++) hacc[k] += sxb[(c0+k)*99+l]*w0;
            }
            __syncthreads();
        }
        #pragma unroll
        for (int k=0;k<4;k++) shh[(c0+k)*33 + s0] = hacc[k];
        for (int i=tid; i<128*64; i+=THR) wz[(i/64)*65 + (i%64)] = hzw[i];
        __syncthreads();
        for (int i=tid; i<128*32; i+=THR){
            int o=i/32, s=i%32;
            float acc = 0.f;
            const float* wr = wz + o*65;
            #pragma unroll 8
            for (int c=0;c<64;c++) acc += wr[c]*shh[c*33+s];
            zz[o*33+s] = acc;
        }
        __syncthreads();
        float Dv = Dp[0];
        for (int i=tid; i<64*32; i+=THR){
            int c=i/32, s=i%32;
            float hv = zz[c*33+s], z = zz[(64+c)*33+s];
            sxb[c*33+s] = hv * (z/(1.f+__expf(-z))) + hv*Dv;
        }
        __syncthreads();
        for (int i=tid; i<64*64; i+=THR) wz[(i/64)*65 + (i%64)] = outw[i];
        __syncthreads();
        for (int i=tid; i<64*32; i+=THR){
            int o=i/32, s=i%32;
            float acc = 0.f;
            const float* wr = wz + o*65;
            #pragma unroll 8
            for (int c=0;c<64;c++) acc += wr[c]*sxb[c*33+s];
            g_h2[((size_t)(b*64 + o))*64 + sh*32 + s] = acc;
        }
    }
    // proj tasks (128)
    for (int t = bid; t < 128; t += NBLK){
        float* sw  = pool;                       // 64*65
        float* sx  = pool + 64*65;               // 64*49
        float* sbn = pool + 64*65 + 64*PT;       // 256
        int b = t / NTt, p0 = (t % NTt) * PT;
        __syncthreads();
        for (int i=tid; i<64*64; i+=THR){ sw[(i/64)*65 + (i%64)] = proj_w[i]; }
        for (int i=tid; i<256; i+=THR) sbn[i] = bn4[i];
        for (int i=tid; i<64*PT; i+=THR){
            int c=i%64, px=i/64;
            sx[c*PT+px] = g_ob[((size_t)b*Ll + p0+px)*64 + c];
        }
        __syncthreads();
        for (int i=tid; i<64*PT; i+=THR){
            int o=i/PT, px=i%PT;
            float acc = 0.f;
            const float* wr = sw + o*65;
            #pragma unroll 8
            for (int j=0;j<64;j++) acc += wr[j]*sx[j*PT+px];
            float xv = x[((size_t)(b*DIMc + 192 + o))*Ll + p0+px];
            g_b4[((size_t)(b*64+o))*Ll + p0+px] = bnf(xv + acc, sbn, o, 64);
        }
    }
    gridsync();

    // ============ PHASE 3: x3 (112 tasks) ============
    for (int t = bid; t < 112; t += NBLK){
        float* cm  = pool;             // 64*57
        float* h2s = pool + 3648;      // 64*65
        int b = t / 14, rc = t % 14;
        int p0 = rc*56;
        __syncthreads();
        for (int i=tid; i<64*64; i+=THR)
            h2s[(i/64)*65 + (i%64)] = g_h2[((size_t)b*64)*64 + i];
        for (int i=tid; i<64*56; i+=THR){
            int s=i/56, lo=i%56;
            int p = p0+lo; int y=p/28, xx=p%28;
            const float* ip = g_bcdt1 + ((size_t)(b*192 + 64 + s))*Ll;
            const float* wc = ssd_dw + (64+s)*9;
            float acc = 0.f;
            #pragma unroll
            for (int ky=0; ky<3; ky++){
                int yy=y+ky-1; if ((unsigned)yy>=28u) continue;
                #pragma unroll
                for (int kx=0; kx<3; kx++){
                    int xw=xx+kx-1; if ((unsigned)xw>=28u) continue;
                    acc += wc[ky*3+kx]*ip[yy*28+xw];
                }
            }
            cm[s*57+lo] = acc;
        }
        __syncthreads();
        int cg = tid & 15, pg = tid >> 4;        // 16 c-groups x 32 px-groups
        int c0 = cg*4, px0 = pg*2;
        if (px0 < 56){
            float acc[4][2];
            #pragma unroll
            for (int k=0;k<4;k++){ acc[k][0]=0.f; acc[k][1]=0.f; }
            #pragma unroll 4
            for (int s=0; s<64; s++){
                float c0v = cm[s*57+px0], c1v = cm[s*57+px0+1];
                #pragma unroll
                for (int k=0;k<4;k++){
                    float hv = h2s[(c0+k)*65 + s];
                    acc[k][0] += hv*c0v; acc[k][1] += hv*c1v;
                }
            }
            #pragma unroll
            for (int k=0;k<4;k++){
                g_b3[((size_t)(b*64 + c0+k))*Ll + p0+px0]   = acc[k][0];
                g_b3[((size_t)(b*64 + c0+k))*Ll + p0+px0+1] = acc[k][1];
            }
        }
    }
    gridsync();

    // ============ PHASE 4: m1 (512 tasks) ============
    for (int t = bid; t < 512; t += NBLK){
        float* sw = pool;              // 32*257 = 8224
        float* sx = pool + 8224;       // 256*49
        int b = t >> 6;
        int tile = (t >> 2) & 15;
        int oc = t & 3;
        int p0 = tile*PT;
        __syncthreads();
        for (int i=tid; i<32*256; i+=THR)
            sw[(i/256)*257 + (i%256)] = mlp1_w[(oc*32 + i/256)*256 + (i%256)];
        for (int i=tid; i<256*PT; i+=THR){
            int c=i/PT, px=i%PT;
            const float* src = (c<64) ? g_b1 : (c<128) ? g_b2 : (c<192) ? g_b3 : g_b4;
            sx[i] = src[((size_t)(b*64 + (c&63)))*Ll + p0+px];
        }
        __syncthreads();
        int og = tid % 16, pg = tid / 16;        // 16 o-groups x 32 px-groups
        int o0 = og*2, px0 = pg*2;
        int cnt = PT - px0; if (cnt > 2) cnt = 2; if (cnt < 0) cnt = 0;
        float acc[2][2];
        acc[0][0]=acc[0][1]=acc[1][0]=acc[1][1]=0.f;
        if (cnt > 0){
            for (int c=0;c<256;c++){
                float v0=sw[(o0+0)*257+c], v1=sw[(o0+1)*257+c];
                float x0 = sx[c*PT + px0];
                float x1 = (cnt>1) ? sx[c*PT + px0 + 1] : 0.f;
                acc[0][0]+=v0*x0; acc[1][0]+=v1*x0;
                acc[0][1]+=v0*x1; acc[1][1]+=v1*x1;
            }
            #pragma unroll
            for (int k=0;k<2;k++)
                for (int j=0;j<cnt;j++){
                    int o = oc*32 + o0 + k;
                    float v = bnf(acc[k][j], bn_m, o, 128);
                    g_m1[((size_t)(b*128 + o))*Ll + p0+px0+j] = fmaxf(v, 0.f);
                }
        }
    }
    gridsync();

    // ============ PHASE 5: m2 (512 tasks) ============
    for (int t = bid; t < 512; t += NBLK){
        float* sw = pool;              // 64*129 = 8256
        float* sx = pool + 8256;       // 128*49
        int b = t >> 6;
        int tile = (t >> 2) & 15;
        int oc = t & 3;
        int p0 = tile*PT;
        __syncthreads();
        for (int i=tid; i<64*128; i+=THR)
            sw[(i/128)*129 + (i%128)] = mlp2_w[(oc*64 + i/128)*128 + (i%128)];
        for (int i=tid; i<128*PT; i+=THR){
            int c=i/PT, px=i%PT;
            sx[i] = g_m1[((size_t)(b*128 + c))*Ll + p0+px];
        }
        __syncthreads();
        int og = tid % 32, pg = tid / 32;        // 32 o-groups x 16 px-groups
        int o0 = og*2, px0 = pg*4;
        int cnt = PT - px0; if (cnt > 4) cnt = 4; if (cnt < 0) cnt = 0;
        float acc[2][4];
        #pragma unroll
        for (int k=0;k<2;k++)
            #pragma unroll
            for (int j=0;j<4;j++) acc[k][j]=0.f;
        if (cnt > 0){
            for (int c=0;c<128;c++){
                float v0=sw[(o0+0)*129+c], v1=sw[(o0+1)*129+c];
                #pragma unroll 4
                for (int j=0;j<4;j++){
                    if (j<cnt){
                        float xx = sx[c*PT + px0 + j];
                        acc[0][j]+=v0*xx; acc[1][j]+=v1*xx;
                    }
                }
            }
            #pragma unroll
            for (int k=0;k<2;k++)
                for (int j=0;j<cnt;j++){
                    int o = oc*64 + o0 + k;
                    size_t idx = ((size_t)(b*DIMc + o))*Ll + p0+px0+j;
                    out[idx] = x[idx] + bnf(acc[k][j], bn1, o, 256);
                }
        }
    }
}

// ---------------- launch ----------------
extern "C" void kernel_launch(void* const* d_in, const int* in_sizes, int n_in,
                              void* d_out, int out_size){
    const float* x       = (const float*)d_in[0];
    const float* dw1_w   = (const float*)d_in[1];
    const float* dw1_b   = (const float*)d_in[2];
    const float* bn_dw1  = (const float*)d_in[3];
    const float* f1_w    = (const float*)d_in[4];
    const float* f1_b    = (const float*)d_in[5];
    const float* f2_w    = (const float*)d_in[6];
    const float* f2_b    = (const float*)d_in[7];
    const float* g_w     = (const float*)d_in[8];
    const float* g_b     = (const float*)d_in[9];
    const float* bn_g    = (const float*)d_in[10];
    const float* dw2_w   = (const float*)d_in[11];
    const float* dw2_b   = (const float*)d_in[12];
    const float* hatt1_w = (const float*)d_in[13];
    const float* vatt1_w = (const float*)d_in[14];
    const float* hatt2_w = (const float*)d_in[15];
    const float* vatt2_w = (const float*)d_in[16];
    const float* bn_mra  = (const float*)d_in[17];
    const float* bcdt_w  = (const float*)d_in[18];
    const float* ssd_dw_w= (const float*)d_in[19];
    const float* hz_w    = (const float*)d_in[20];
    const float* out_w   = (const float*)d_in[21];
    const float* A_param = (const float*)d_in[22];
    const float* D_param = (const float*)d_in[23];
    const float* qkv_w   = (const float*)d_in[24];
    const float* proj_w  = (const float*)d_in[25];
    const float* bn_n4   = (const float*)d_in[26];
    const float* mlp1_w  = (const float*)d_in[27];
    const float* bn_mlp  = (const float*)d_in[28];
    const float* mlp2_w  = (const float*)d_in[29];
    const float* bn_n1   = (const float*)d_in[30];
    float* out = (float*)d_out;
    (void)n_in; (void)in_sizes; (void)out_size;

    // pool must cover the largest stage: star = 25792 floats = 103168 bytes
    const int SMEM = 25792 * 4;
    cudaFuncSetAttribute(k_all, cudaFuncAttributeMaxDynamicSharedMemorySize, SMEM);

    k_all<<<NBLK, THR, SMEM>>>(x, dw1_w, dw1_b, bn_dw1,
                               f1_w, f1_b, f2_w, f2_b, g_w, g_b, bn_g,
                               dw2_w, dw2_b,
                               hatt1_w, vatt1_w, hatt2_w, vatt2_w, bn_mra,
                               bcdt_w, ssd_dw_w, hz_w, out_w, A_param, D_param,
                               qkv_w, proj_w, bn_n4,
                               mlp1_w, bn_mlp, mlp2_w, bn_n1, out);
}